// round 6
// baseline (speedup 1.0000x reference)
#include <cuda_runtime.h>
#include <cuda_bf16.h>
#include <stdint.h>

// ApplyRotary: T=32768 tokens, H=32 heads, D=128, ROPE_DIM=64.
// out[t,h,d<32]    =  x[d]*cos[d] - x[d+32]*sin[d]
// out[t,h,32<=d<64]=  x[d]*cos[d] + x[d-32]*sin[d]
// out[t,h,d>=64]   =  x[d]
//
// One WARP per TOKEN, 256-bit ld/st, double-buffered (R4 base).
// R5 deltas: (a) st.global.cs — evict-first for the never-re-read output
// stream, smoothing L2 writeback against the read stream; (b) immediate
// byte offsets baked into the PTX (one base register per stream instead
// of per-op 64-bit address chains).

#define N_TOK   32768
#define N_HEAD  32
#define ROPE    64

template <int OFF>
__device__ __forceinline__ void ldg256(const float* p, float r[8]) {
    asm volatile("ld.global.nc.v8.f32 {%0,%1,%2,%3,%4,%5,%6,%7}, [%8+%9];"
        : "=f"(r[0]), "=f"(r[1]), "=f"(r[2]), "=f"(r[3]),
          "=f"(r[4]), "=f"(r[5]), "=f"(r[6]), "=f"(r[7])
        : "l"(p), "n"(OFF));
}

template <int OFF>
__device__ __forceinline__ void stg256(float* p, const float r[8]) {
    asm volatile("st.global.cs.v8.f32 [%0+%9], {%1,%2,%3,%4,%5,%6,%7,%8};"
        :: "l"(p),
           "f"(r[0]), "f"(r[1]), "f"(r[2]), "f"(r[3]),
           "f"(r[4]), "f"(r[5]), "f"(r[6]), "f"(r[7]),
           "n"(OFF)
        : "memory");
}

__global__ __launch_bounds__(256, 3) void rope_kernel(
    const float* __restrict__ in,
    const float* __restrict__ sin_c,
    const float* __restrict__ cos_c,
    const int*   __restrict__ cu,
    float*       __restrict__ out)
{
    const int warp = threadIdx.x >> 5;
    const int lane = threadIdx.x & 31;
    const int t    = blockIdx.x * 8 + warp;   // one token per warp
    const int il   = lane & 15;               // lane within 16-lane head span

    // Branchless binary search: largest idx in [0,16] with cu[idx] <= t.
    int lo = 0;
#pragma unroll
    for (int half = 16; half > 0; half >>= 1) {
        int mid = lo + half;
        if (mid <= 16 && __ldg(cu + mid) <= t) lo = mid;
    }
    const int off = t - __ldg(cu + lo);

    // sin/cos for this lane's 8 rope dims (only il<8 is in the rope region).
    float s8[8], c8[8];
#pragma unroll
    for (int k = 0; k < 8; k++) { s8[k] = 0.f; c8[k] = 0.f; }
    if (il < 8) {
        ldg256<0>(sin_c + (size_t)off * ROPE + 8 * il, s8);
        ldg256<0>(cos_c + (size_t)off * ROPE + 8 * il, c8);
    }
    const float sg   = (il < 4) ? -1.0f : 1.0f;
    const bool  rope = (il < 8);

    const float* inb  = in  + (size_t)t * (N_HEAD * 128) + 8 * lane;
    float*       outb = out + (size_t)t * (N_HEAD * 128) + 8 * lane;

    // 4 chunks of 8 heads (4 x 1KB ld each), double-buffered, fully
    // unrolled with immediate offsets (CH = chunk index, compile-time).
    float v[4][8], w[4][8];
#pragma unroll
    for (int j = 0; j < 4; j++)
        ldg256<0>(inb + 256 * j, v[j]);   // offsets folded below via macro path

    // Re-issue with immediate offsets for the steady state:
#define LD_CHUNK(buf, CH)                                              \
    do {                                                               \
        ldg256<(CH)*4096 + 0   >(inb, (buf)[0]);                       \
        ldg256<(CH)*4096 + 1024>(inb, (buf)[1]);                       \
        ldg256<(CH)*4096 + 2048>(inb, (buf)[2]);                       \
        ldg256<(CH)*4096 + 3072>(inb, (buf)[3]);                       \
    } while (0)

#define ST_CHUNK(buf, CH)                                              \
    do {                                                               \
        float r[8];                                                    \
        _Pragma("unroll")                                              \
        for (int k = 0; k < 8; k++) {                                  \
            const float q = __shfl_xor_sync(0xffffffffu, (buf)[0][k], 4); \
            r[k] = rope ? fmaf(sg * q, s8[k], (buf)[0][k] * c8[k]) : (buf)[0][k]; \
        }                                                              \
        stg256<(CH)*4096 + 0>(outb, r);                                \
        _Pragma("unroll")                                              \
        for (int k = 0; k < 8; k++) {                                  \
            const float q = __shfl_xor_sync(0xffffffffu, (buf)[1][k], 4); \
            r[k] = rope ? fmaf(sg * q, s8[k], (buf)[1][k] * c8[k]) : (buf)[1][k]; \
        }                                                              \
        stg256<(CH)*4096 + 1024>(outb, r);                             \
        _Pragma("unroll")                                              \
        for (int k = 0; k < 8; k++) {                                  \
            const float q = __shfl_xor_sync(0xffffffffu, (buf)[2][k], 4); \
            r[k] = rope ? fmaf(sg * q, s8[k], (buf)[2][k] * c8[k]) : (buf)[2][k]; \
        }                                                              \
        stg256<(CH)*4096 + 2048>(outb, r);                             \
        _Pragma("unroll")                                              \
        for (int k = 0; k < 8; k++) {                                  \
            const float q = __shfl_xor_sync(0xffffffffu, (buf)[3][k], 4); \
            r[k] = rope ? fmaf(sg * q, s8[k], (buf)[3][k] * c8[k]) : (buf)[3][k]; \
        }                                                              \
        stg256<(CH)*4096 + 3072>(outb, r);                             \
    } while (0)

    // Ping-pong across 4 chunks (8 heads each): v holds chunk0 already? No —
    // restart cleanly: chunk0 into v, then pipeline.
    LD_CHUNK(v, 0);
    LD_CHUNK(w, 1);
    ST_CHUNK(v, 0);
    LD_CHUNK(v, 2);
    ST_CHUNK(w, 1);
    LD_CHUNK(w, 3);
    ST_CHUNK(v, 2);
    ST_CHUNK(w, 3);

#undef LD_CHUNK
#undef ST_CHUNK
}

extern "C" void kernel_launch(void* const* d_in, const int* in_sizes, int n_in,
                              void* d_out, int out_size)
{
    const float* in    = (const float*)d_in[0];
    const float* sin_c = (const float*)d_in[1];
    const float* cos_c = (const float*)d_in[2];
    const int*   cu    = (const int*)  d_in[3];
    float*       out   = (float*)d_out;

    const int blocks = N_TOK / 8;   // 4096 blocks, 8 warps each
    rope_kernel<<<blocks, 256>>>(in, sin_c, cos_c, cu, out);
}

// round 7
// speedup vs baseline: 1.0098x; 1.0098x over previous
#include <cuda_runtime.h>
#include <cuda_bf16.h>
#include <stdint.h>

// ApplyRotary: T=32768 tokens, H=32 heads, D=128, ROPE_DIM=64.
// out[t,h,d<32]    =  x[d]*cos[d] - x[d+32]*sin[d]
// out[t,h,32<=d<64]=  x[d]*cos[d] + x[d-32]*sin[d]
// out[t,h,d>=64]   =  x[d]
//
// One WARP per TOKEN, 256-bit ld/st, double-buffered (R4 base — best
// measured). R6 delta: L2::evict_first on BOTH the input and output
// streams so the 1 GB streaming footprint rotates through a thin L2
// slice instead of contending with dirty writeback lines.

#define N_TOK   32768
#define N_HEAD  32
#define ROPE    64

__device__ __forceinline__ void ldg256_ef(const float* p, float r[8]) {
    asm volatile("ld.global.nc.L2::evict_first.v8.f32 {%0,%1,%2,%3,%4,%5,%6,%7}, [%8];"
        : "=f"(r[0]), "=f"(r[1]), "=f"(r[2]), "=f"(r[3]),
          "=f"(r[4]), "=f"(r[5]), "=f"(r[6]), "=f"(r[7])
        : "l"(p));
}

__device__ __forceinline__ void ldg256(const float* p, float r[8]) {
    asm volatile("ld.global.nc.v8.f32 {%0,%1,%2,%3,%4,%5,%6,%7}, [%8];"
        : "=f"(r[0]), "=f"(r[1]), "=f"(r[2]), "=f"(r[3]),
          "=f"(r[4]), "=f"(r[5]), "=f"(r[6]), "=f"(r[7])
        : "l"(p));
}

__device__ __forceinline__ void stg256_ef(float* p, const float r[8]) {
    asm volatile("st.global.L2::evict_first.v8.f32 [%0], {%1,%2,%3,%4,%5,%6,%7,%8};"
        :: "l"(p),
           "f"(r[0]), "f"(r[1]), "f"(r[2]), "f"(r[3]),
           "f"(r[4]), "f"(r[5]), "f"(r[6]), "f"(r[7])
        : "memory");
}

__global__ __launch_bounds__(256, 3) void rope_kernel(
    const float* __restrict__ in,
    const float* __restrict__ sin_c,
    const float* __restrict__ cos_c,
    const int*   __restrict__ cu,
    float*       __restrict__ out)
{
    const int warp = threadIdx.x >> 5;
    const int lane = threadIdx.x & 31;
    const int t    = blockIdx.x * 8 + warp;   // one token per warp
    const int il   = lane & 15;               // lane within 16-lane head span

    // Branchless binary search: largest idx in [0,16] with cu[idx] <= t.
    int lo = 0;
#pragma unroll
    for (int half = 16; half > 0; half >>= 1) {
        int mid = lo + half;
        if (mid <= 16 && __ldg(cu + mid) <= t) lo = mid;
    }
    const int off = t - __ldg(cu + lo);

    // sin/cos for this lane's 8 rope dims (reused tables: default policy).
    float s8[8], c8[8];
#pragma unroll
    for (int k = 0; k < 8; k++) { s8[k] = 0.f; c8[k] = 0.f; }
    if (il < 8) {
        ldg256(sin_c + (size_t)off * ROPE + 8 * il, s8);
        ldg256(cos_c + (size_t)off * ROPE + 8 * il, c8);
    }
    const float sg   = (il < 4) ? -1.0f : 1.0f;
    const bool  rope = (il < 8);

    const float* inb  = in  + (size_t)t * (N_HEAD * 128) + 8 * lane;
    float*       outb = out + (size_t)t * (N_HEAD * 128) + 8 * lane;

    // 8 chunks of 4 heads (2 x 1KB LDG.256 each), double-buffered.
    float v[2][8], w[2][8];
#pragma unroll
    for (int j = 0; j < 2; j++)
        ldg256_ef(inb + 256 * j, v[j]);

#pragma unroll
    for (int c = 0; c < 8; c++) {
        if (c < 7) {
#pragma unroll
            for (int j = 0; j < 2; j++)
                ldg256_ef(inb + 512 * (c + 1) + 256 * j, w[j]);
        }

#pragma unroll
        for (int j = 0; j < 2; j++) {
            float r[8];
#pragma unroll
            for (int k = 0; k < 8; k++) {
                const float q = __shfl_xor_sync(0xffffffffu, v[j][k], 4);
                r[k] = rope ? fmaf(sg * q, s8[k], v[j][k] * c8[k]) : v[j][k];
            }
            stg256_ef(outb + 512 * c + 256 * j, r);
        }

#pragma unroll
        for (int j = 0; j < 2; j++)
#pragma unroll
            for (int k = 0; k < 8; k++)
                v[j][k] = w[j][k];
    }
}

extern "C" void kernel_launch(void* const* d_in, const int* in_sizes, int n_in,
                              void* d_out, int out_size)
{
    const float* in    = (const float*)d_in[0];
    const float* sin_c = (const float*)d_in[1];
    const float* cos_c = (const float*)d_in[2];
    const int*   cu    = (const int*)  d_in[3];
    float*       out   = (float*)d_out;

    const int blocks = N_TOK / 8;   // 4096 blocks, 8 warps each
    rope_kernel<<<blocks, 256>>>(in, sin_c, cos_c, cu, out);
}

// round 9
// speedup vs baseline: 1.0165x; 1.0066x over previous
#include <cuda_runtime.h>
#include <cuda_bf16.h>
#include <stdint.h>

// ApplyRotary: T=32768 tokens, H=32 heads, D=128, ROPE_DIM=64.
// out[t,h,d<32]    =  x[d]*cos[d] - x[d+32]*sin[d]
// out[t,h,32<=d<64]=  x[d]*cos[d] + x[d-32]*sin[d]
// out[t,h,d>=64]   =  x[d]
//
// One WARP per TOKEN, 256-bit ld/st, L2::evict_first on both streams
// (R6 base). R7 delta: 3-stage software pipeline — TWO chunks (4 KB)
// of reads permanently in flight per warp, removing the chunk-boundary
// issue bubble of the 2-stage version.

#define N_TOK   32768
#define N_HEAD  32
#define ROPE    64

__device__ __forceinline__ void ldg256_ef(const float* p, float r[8]) {
    asm volatile("ld.global.nc.L2::evict_first.v8.f32 {%0,%1,%2,%3,%4,%5,%6,%7}, [%8];"
        : "=f"(r[0]), "=f"(r[1]), "=f"(r[2]), "=f"(r[3]),
          "=f"(r[4]), "=f"(r[5]), "=f"(r[6]), "=f"(r[7])
        : "l"(p));
}

__device__ __forceinline__ void ldg256(const float* p, float r[8]) {
    asm volatile("ld.global.nc.v8.f32 {%0,%1,%2,%3,%4,%5,%6,%7}, [%8];"
        : "=f"(r[0]), "=f"(r[1]), "=f"(r[2]), "=f"(r[3]),
          "=f"(r[4]), "=f"(r[5]), "=f"(r[6]), "=f"(r[7])
        : "l"(p));
}

__device__ __forceinline__ void stg256_ef(float* p, const float r[8]) {
    asm volatile("st.global.L2::evict_first.v8.f32 [%0], {%1,%2,%3,%4,%5,%6,%7,%8};"
        :: "l"(p),
           "f"(r[0]), "f"(r[1]), "f"(r[2]), "f"(r[3]),
           "f"(r[4]), "f"(r[5]), "f"(r[6]), "f"(r[7])
        : "memory");
}

__global__ __launch_bounds__(256, 2) void rope_kernel(
    const float* __restrict__ in,
    const float* __restrict__ sin_c,
    const float* __restrict__ cos_c,
    const int*   __restrict__ cu,
    float*       __restrict__ out)
{
    const int warp = threadIdx.x >> 5;
    const int lane = threadIdx.x & 31;
    const int t    = blockIdx.x * 8 + warp;   // one token per warp
    const int il   = lane & 15;               // lane within 16-lane head span

    // Branchless binary search: largest idx in [0,16] with cu[idx] <= t.
    int lo = 0;
#pragma unroll
    for (int half = 16; half > 0; half >>= 1) {
        int mid = lo + half;
        if (mid <= 16 && __ldg(cu + mid) <= t) lo = mid;
    }
    const int off = t - __ldg(cu + lo);

    // sin/cos for this lane's 8 rope dims (reused tables: default policy).
    float s8[8], c8[8];
#pragma unroll
    for (int k = 0; k < 8; k++) { s8[k] = 0.f; c8[k] = 0.f; }
    if (il < 8) {
        ldg256(sin_c + (size_t)off * ROPE + 8 * il, s8);
        ldg256(cos_c + (size_t)off * ROPE + 8 * il, c8);
    }
    const float sg   = (il < 4) ? -1.0f : 1.0f;
    const bool  rope = (il < 8);

    const float* inb  = in  + (size_t)t * (N_HEAD * 128) + 8 * lane;
    float*       outb = out + (size_t)t * (N_HEAD * 128) + 8 * lane;

    // 8 chunks of 4 heads (2 x 1KB LDG.256 each). 3-stage pipeline:
    // buffers b[0..2] rotate; chunks c and c+1 are always in flight
    // while chunk c-? is being computed/stored.
    float b[3][2][8];

#pragma unroll
    for (int j = 0; j < 2; j++) ldg256_ef(inb + j * 256,       b[0][j]);
#pragma unroll
    for (int j = 0; j < 2; j++) ldg256_ef(inb + 512 + j * 256, b[1][j]);

#pragma unroll
    for (int c = 0; c < 8; c++) {
        const int cur = c % 3;
        const int nxt = (c + 2) % 3;
        if (c < 6) {
#pragma unroll
            for (int j = 0; j < 2; j++)
                ldg256_ef(inb + 512 * (c + 2) + j * 256, b[nxt][j]);
        }

#pragma unroll
        for (int j = 0; j < 2; j++) {
            float r[8];
#pragma unroll
            for (int k = 0; k < 8; k++) {
                const float q = __shfl_xor_sync(0xffffffffu, b[cur][j][k], 4);
                r[k] = rope ? fmaf(sg * q, s8[k], b[cur][j][k] * c8[k]) : b[cur][j][k];
            }
            stg256_ef(outb + 512 * c + j * 256, r);
        }
    }
}

extern "C" void kernel_launch(void* const* d_in, const int* in_sizes, int n_in,
                              void* d_out, int out_size)
{
    const float* in    = (const float*)d_in[0];
    const float* sin_c = (const float*)d_in[1];
    const float* cos_c = (const float*)d_in[2];
    const int*   cu    = (const int*)  d_in[3];
    float*       out   = (float*)d_out;

    const int blocks = N_TOK / 8;   // 4096 blocks, 8 warps each
    rope_kernel<<<blocks, 256>>>(in, sin_c, cos_c, cu, out);
}